// round 1
// baseline (speedup 1.0000x reference)
#include <cuda_runtime.h>

#define N_ATOMS 10000
#define N_PAIRS 500000
#define N_DESC  64

// Precomputed per-atom table: g[n,d] = (1 - tanh^2(coeffs*w1+b1)) * w1[d] * w_last[d]
__device__ float g_table[N_ATOMS * N_DESC];

// ---------------------------------------------------------------------------
// Kernel 0: initialize output. d_out[0] = b_last, forces = 0.
// ---------------------------------------------------------------------------
__global__ void init_out_kernel(float* __restrict__ out, const float* __restrict__ b_last,
                                int out_size) {
    int i = blockIdx.x * blockDim.x + threadIdx.x;
    if (i >= out_size) return;
    out[i] = (i == 0) ? b_last[0] : 0.0f;
}

// ---------------------------------------------------------------------------
// Kernel 1: build g table + accumulate energy.
// One thread per (atom, descriptor). 640k threads.
// ---------------------------------------------------------------------------
__global__ void table_energy_kernel(const float* __restrict__ coeffs,
                                    const float* __restrict__ w1,
                                    const float* __restrict__ b1,
                                    const float* __restrict__ w_last,
                                    float* __restrict__ out) {
    int idx = blockIdx.x * blockDim.x + threadIdx.x;
    float e_contrib = 0.0f;
    if (idx < N_ATOMS * N_DESC) {
        int d = idx & (N_DESC - 1);
        float w = w1[d];
        float wl = w_last[d];
        float e = tanhf(fmaf(coeffs[idx], w, b1[d]));
        g_table[idx] = (1.0f - e * e) * w * wl;
        e_contrib = e * wl;
    }

    // block reduction of energy contribution
    __shared__ float red[256 / 32];
    #pragma unroll
    for (int o = 16; o > 0; o >>= 1)
        e_contrib += __shfl_xor_sync(0xFFFFFFFFu, e_contrib, o);
    int lane = threadIdx.x & 31;
    int wid = threadIdx.x >> 5;
    if (lane == 0) red[wid] = e_contrib;
    __syncthreads();
    if (wid == 0) {
        float v = (lane < (blockDim.x >> 5)) ? red[lane] : 0.0f;
        #pragma unroll
        for (int o = 16; o > 0; o >>= 1)
            v += __shfl_xor_sync(0xFFFFFFFFu, v, o);
        if (lane == 0)
            atomicAdd(out, v * (1.0f / (float)N_ATOMS));
    }
}

// ---------------------------------------------------------------------------
// Kernel 2: pair contraction + scatter.
// One warp per pair. Each lane owns 2 descriptors (float2).
//   s[x] = sum_d g[c,d] * derivs[x,p,d];  out_f[x, neigh] += -s[x]
// ---------------------------------------------------------------------------
__global__ void __launch_bounds__(256) pair_kernel(
    const float* __restrict__ derivs,          // [3, N_PAIRS, 64]
    const int* __restrict__ central,
    const int* __restrict__ neigh,
    float* __restrict__ out_f)                 // d_out + 1, layout [3, N_ATOMS]
{
    unsigned gtid = blockIdx.x * blockDim.x + threadIdx.x;
    unsigned p = gtid >> 5;
    unsigned lane = threadIdx.x & 31;
    if (p >= N_PAIRS) return;

    int c  = __ldg(central + p);
    int nb = __ldg(neigh + p);

    const float2* grow = (const float2*)(g_table + (size_t)c * N_DESC);
    float2 g = grow[lane];

    const float* base = derivs + (size_t)p * N_DESC + lane * 2;
    const size_t dimstride = (size_t)N_PAIRS * N_DESC;
    float2 v0 = *(const float2*)(base);
    float2 v1 = *(const float2*)(base + dimstride);
    float2 v2 = *(const float2*)(base + 2 * dimstride);

    float s0 = fmaf(v0.x, g.x, v0.y * g.y);
    float s1 = fmaf(v1.x, g.x, v1.y * g.y);
    float s2 = fmaf(v2.x, g.x, v2.y * g.y);

    #pragma unroll
    for (int o = 16; o > 0; o >>= 1) {
        s0 += __shfl_xor_sync(0xFFFFFFFFu, s0, o);
        s1 += __shfl_xor_sync(0xFFFFFFFFu, s1, o);
        s2 += __shfl_xor_sync(0xFFFFFFFFu, s2, o);
    }

    if (lane < 3) {
        float s = (lane == 0) ? s0 : (lane == 1) ? s1 : s2;
        atomicAdd(out_f + (size_t)lane * N_ATOMS + nb, -s);
    }
}

// ---------------------------------------------------------------------------
extern "C" void kernel_launch(void* const* d_in, const int* in_sizes, int n_in,
                              void* d_out, int out_size) {
    const float* coeffs   = (const float*)d_in[0];   // [1, N_ATOMS, 64]
    const float* derivs   = (const float*)d_in[1];   // [1, 3, N_PAIRS, 64]
    const float* w1       = (const float*)d_in[2];
    const float* b1       = (const float*)d_in[3];
    const float* w_last   = (const float*)d_in[4];
    const float* b_last   = (const float*)d_in[5];
    const int*   central  = (const int*)d_in[6];
    const int*   neigh    = (const int*)d_in[7];
    float* out = (float*)d_out;                      // [0]=energy, [1..30000]=forces [3,N_ATOMS]

    // 1) init output (energy = b_last, forces = 0)
    {
        int n = out_size;
        init_out_kernel<<<(n + 255) / 256, 256>>>(out, b_last, n);
    }

    // 2) g table + energy
    {
        int n = N_ATOMS * N_DESC;
        table_energy_kernel<<<(n + 255) / 256, 256>>>(coeffs, w1, b1, w_last, out);
    }

    // 3) pair contraction + scatter (one warp per pair)
    {
        long long threads = (long long)N_PAIRS * 32;
        int blocks = (int)((threads + 255) / 256);
        pair_kernel<<<blocks, 256>>>(derivs, central, neigh, out + 1);
    }
}

// round 2
// speedup vs baseline: 1.4360x; 1.4360x over previous
#include <cuda_runtime.h>

#define N_ATOMS 10000
#define N_PAIRS 500000
#define N_DESC  64

// Precomputed per-atom table: g[n,d] = (1 - tanh^2(coeffs*w1+b1)) * w1[d] * w_last[d]
__device__ float g_table[N_ATOMS * N_DESC];

// ---------------------------------------------------------------------------
// Kernel 1: build g table + accumulate energy into out[0] (pre-zeroed by
// memset node). Thread 0 also adds b_last. One thread per (atom, descriptor).
// ---------------------------------------------------------------------------
__global__ void table_energy_kernel(const float* __restrict__ coeffs,
                                    const float* __restrict__ w1,
                                    const float* __restrict__ b1,
                                    const float* __restrict__ w_last,
                                    const float* __restrict__ b_last,
                                    float* __restrict__ out) {
    int idx = blockIdx.x * blockDim.x + threadIdx.x;
    float e_contrib = 0.0f;
    if (idx < N_ATOMS * N_DESC) {
        int d = idx & (N_DESC - 1);
        float w = w1[d];
        float wl = w_last[d];
        float e = tanhf(fmaf(coeffs[idx], w, b1[d]));
        g_table[idx] = (1.0f - e * e) * w * wl;
        e_contrib = e * wl;
    }
    if (idx == 0) atomicAdd(out, b_last[0]);

    // block reduction of energy contribution
    __shared__ float red[256 / 32];
    #pragma unroll
    for (int o = 16; o > 0; o >>= 1)
        e_contrib += __shfl_xor_sync(0xFFFFFFFFu, e_contrib, o);
    int lane = threadIdx.x & 31;
    int wid = threadIdx.x >> 5;
    if (lane == 0) red[wid] = e_contrib;
    __syncthreads();
    if (wid == 0) {
        float v = (lane < (blockDim.x >> 5)) ? red[lane] : 0.0f;
        #pragma unroll
        for (int o = 16; o > 0; o >>= 1)
            v += __shfl_xor_sync(0xFFFFFFFFu, v, o);
        if (lane == 0)
            atomicAdd(out, v * (1.0f / (float)N_ATOMS));
    }
}

// ---------------------------------------------------------------------------
// Kernel 2: pair contraction + scatter.
// TWO pairs per warp: lanes 0-15 -> pair 2w, lanes 16-31 -> pair 2w+1.
// Each lane owns 4 descriptors (float4). Each deriv load is one warp-wide
// 512 B contiguous LDG.128 (both pairs' rows are adjacent in memory).
// Derivs loaded with __ldcs (streaming, evict-first) so the L2 keeps
// g_table and the force accumulator resident.
// ---------------------------------------------------------------------------
__global__ void __launch_bounds__(256) pair_kernel(
    const float* __restrict__ derivs,          // [3, N_PAIRS, 64]
    const int* __restrict__ central,
    const int* __restrict__ neigh,
    float* __restrict__ out_f)                 // d_out + 1, layout [3, N_ATOMS]
{
    unsigned gtid = blockIdx.x * blockDim.x + threadIdx.x;
    unsigned warp = gtid >> 5;
    unsigned lane = threadIdx.x & 31;
    unsigned p = warp * 2 + (lane >> 4);       // pair served by this lane
    if (p >= N_PAIRS) return;
    unsigned l16 = lane & 15;

    int c  = __ldg(central + p);
    int nb = __ldg(neigh + p);

    // gather g row (L2-resident), 4 descriptors per lane
    float4 g = *(const float4*)(g_table + (size_t)c * N_DESC + l16 * 4);

    const float* base = derivs + (size_t)p * N_DESC + l16 * 4;
    const size_t ds = (size_t)N_PAIRS * N_DESC;
    float4 v0 = __ldcs((const float4*)(base));
    float4 v1 = __ldcs((const float4*)(base + ds));
    float4 v2 = __ldcs((const float4*)(base + 2 * ds));

    float s0 = fmaf(v0.x, g.x, fmaf(v0.y, g.y, fmaf(v0.z, g.z, v0.w * g.w)));
    float s1 = fmaf(v1.x, g.x, fmaf(v1.y, g.y, fmaf(v1.z, g.z, v1.w * g.w)));
    float s2 = fmaf(v2.x, g.x, fmaf(v2.y, g.y, fmaf(v2.z, g.z, v2.w * g.w)));

    // reduce within each 16-lane half (xor offsets stay inside the half)
    #pragma unroll
    for (int o = 8; o > 0; o >>= 1) {
        s0 += __shfl_xor_sync(0xFFFFFFFFu, s0, o);
        s1 += __shfl_xor_sync(0xFFFFFFFFu, s1, o);
        s2 += __shfl_xor_sync(0xFFFFFFFFu, s2, o);
    }

    if (l16 < 3) {
        float s = (l16 == 0) ? s0 : (l16 == 1) ? s1 : s2;
        atomicAdd(out_f + (size_t)l16 * N_ATOMS + nb, -s);
    }
}

// ---------------------------------------------------------------------------
extern "C" void kernel_launch(void* const* d_in, const int* in_sizes, int n_in,
                              void* d_out, int out_size) {
    const float* coeffs   = (const float*)d_in[0];   // [1, N_ATOMS, 64]
    const float* derivs   = (const float*)d_in[1];   // [1, 3, N_PAIRS, 64]
    const float* w1       = (const float*)d_in[2];
    const float* b1       = (const float*)d_in[3];
    const float* w_last   = (const float*)d_in[4];
    const float* b_last   = (const float*)d_in[5];
    const int*   central  = (const int*)d_in[6];
    const int*   neigh    = (const int*)d_in[7];
    float* out = (float*)d_out;                      // [0]=energy, [1..30000]=forces [3,N_ATOMS]

    // 1) zero output (memset node — graph-capturable, no alloc)
    cudaMemsetAsync(out, 0, (size_t)out_size * sizeof(float));

    // 2) g table + energy (adds b_last + mean(e*w_last) into out[0])
    {
        int n = N_ATOMS * N_DESC;
        table_energy_kernel<<<(n + 255) / 256, 256>>>(coeffs, w1, b1, w_last, b_last, out);
    }

    // 3) pair contraction + scatter (two pairs per warp)
    {
        int warps = (N_PAIRS + 1) / 2;
        int blocks = (warps * 32 + 255) / 256;
        pair_kernel<<<blocks, 256>>>(derivs, central, neigh, out + 1);
    }
}